// round 9
// baseline (speedup 1.0000x reference)
#include <cuda_runtime.h>

#define N_NODES 100000
#define N_EDGES 1600000
#define D 64
#define N_RELS 200
#define SLOPE 0.01f
#define SCAN_NB 196            // ceil(100000/512)

// Scratch (static device globals — no allocation anywhere)
__device__ float g_hW[N_NODES * D];      // h @ W[:D]
__device__ float g_relW[N_RELS * D];     // rel_emb @ W[D:]
__device__ float g_ssrc[N_NODES];
__device__ float g_sdst[N_NODES];
__device__ float g_srel[N_RELS];
__device__ int   g_cnt[N_NODES];         // dst histogram
__device__ int   g_off[N_NODES + 1];     // CSR offsets
__device__ int   g_cur[N_NODES];         // scatter cursors
__device__ int   g_bsum[SCAN_NB];        // scan block sums
__device__ int2  g_pe[N_EDGES];          // dst-sorted (src<<8|etype, bits(ex))

__device__ __forceinline__ int warp_incl_scan(int v) {
    #pragma unroll
    for (int o = 1; o < 32; o <<= 1) {
        int t = __shfl_up_sync(0xffffffffu, v, o);
        if ((threadIdx.x & 31) >= o) v += t;
    }
    return v;
}

// ---------------------------------------------------------------------------
// 0) zero histogram
__global__ void k_zero() {
    int i = blockIdx.x * blockDim.x + threadIdx.x;
    if (i < N_NODES) g_cnt[i] = 0;
}

// 1) hW = h@Wn[:D]; out = h@Wl (loop term, fixed up later for zero-deg nodes);
//    s_src = h@a1; s_dst = h@a2.  4 nodes per 256-thread block.
__global__ void k_hw_s(const float* __restrict__ h, const float* __restrict__ Wn,
                       const float* __restrict__ Wl, const float* __restrict__ attn,
                       float* __restrict__ out) {
    __shared__ float sW[D * D];
    __shared__ float sL[D * D];
    __shared__ float sh[4][D];
    __shared__ float part1[8], part2[8];
    int t = threadIdx.x;
    #pragma unroll
    for (int i = t; i < D * D; i += 256) { sW[i] = Wn[i]; sL[i] = Wl[i]; }
    int l = t >> 6, j = t & 63;
    int node = blockIdx.x * 4 + l;
    float v = h[node * D + j];
    sh[l][j] = v;
    float p1 = v * attn[j];
    float p2 = v * attn[D + j];
    #pragma unroll
    for (int o = 16; o; o >>= 1) {
        p1 += __shfl_down_sync(0xffffffffu, p1, o);
        p2 += __shfl_down_sync(0xffffffffu, p2, o);
    }
    int w = t >> 5;
    if ((t & 31) == 0) { part1[w] = p1; part2[w] = p2; }
    __syncthreads();
    if (j == 0) {
        g_ssrc[node] = part1[2 * l] + part1[2 * l + 1];
        g_sdst[node] = part2[2 * l] + part2[2 * l + 1];
    }
    float acc = 0.0f, accL = 0.0f;
    #pragma unroll
    for (int k = 0; k < D; k++) {
        float hv = sh[l][k];
        acc  = fmaf(hv, sW[k * D + j], acc);
        accL = fmaf(hv, sL[k * D + j], accL);
    }
    g_hW[node * D + j] = acc;
    out[node * D + j]  = accL;
}

// 2) relW = rel_emb @ Wn[D:], s_rel = rel_emb @ a3
__global__ void k_rel(const float* __restrict__ rel, const float* __restrict__ Wn,
                      const float* __restrict__ attn) {
    __shared__ float sr[D];
    int r = blockIdx.x, j = threadIdx.x;
    sr[j] = rel[r * D + j];
    __syncthreads();
    float acc = 0.0f;
    #pragma unroll
    for (int k = 0; k < D; k++) acc = fmaf(sr[k], Wn[(D + k) * D + j], acc);
    g_relW[r * D + j] = acc;
    if (j == 0) {
        float s = 0.0f;
        #pragma unroll
        for (int k = 0; k < D; k++) s = fmaf(sr[k], attn[2 * D + k], s);
        g_srel[r] = s;
    }
}

// 3) histogram of dst
__global__ void k_hist(const int* __restrict__ dst) {
    int e = blockIdx.x * blockDim.x + threadIdx.x;
    if (e < N_EDGES) atomicAdd(&g_cnt[dst[e]], 1);
}

// 4a) per-block exclusive scan of g_cnt (512/block)
__global__ void k_scan1() {
    __shared__ int ws[16];
    int i = blockIdx.x * 512 + threadIdx.x;
    int lane = threadIdx.x & 31, wid = threadIdx.x >> 5;
    int v = (i < N_NODES) ? g_cnt[i] : 0;
    int s = warp_incl_scan(v);
    if (lane == 31) ws[wid] = s;
    __syncthreads();
    if (wid == 0) {
        int t = (lane < 16) ? ws[lane] : 0;
        int ts = warp_incl_scan(t);
        if (lane < 16) ws[lane] = ts;
    }
    __syncthreads();
    int excl = s - v + (wid > 0 ? ws[wid - 1] : 0);
    if (i < N_NODES) g_off[i] = excl;
    if (threadIdx.x == 0) g_bsum[blockIdx.x] = ws[15];
}

// 4b) scan of block sums
__global__ void k_scan2() {
    __shared__ int ws[8];
    int tid = threadIdx.x;
    int lane = tid & 31, wid = tid >> 5;
    int v = (tid < SCAN_NB) ? g_bsum[tid] : 0;
    int s = warp_incl_scan(v);
    if (lane == 31) ws[wid] = s;
    __syncthreads();
    if (wid == 0) {
        int t = (lane < 8) ? ws[lane] : 0;
        int ts = warp_incl_scan(t);
        if (lane < 8) ws[lane] = ts;
    }
    __syncthreads();
    int excl = s - v + (wid > 0 ? ws[wid - 1] : 0);
    if (tid < SCAN_NB) g_bsum[tid] = excl;
}

// 4c) add block offsets; init cursors; sentinel
__global__ void k_scan3() {
    int i = blockIdx.x * 512 + threadIdx.x;
    if (i < N_NODES) {
        int o = g_off[i] + g_bsum[blockIdx.x];
        g_off[i] = o;
        g_cur[i] = o;
    }
    if (i == 0) g_off[N_NODES] = N_EDGES;
}

// 5) scatter: ex = exp(score), write dst-sorted packed (pk, ex) as one STG.64
__global__ void k_scatter(const float* __restrict__ etime, const int* __restrict__ src,
                          const int* __restrict__ dst, const int* __restrict__ etype,
                          const float* __restrict__ delta) {
    int e = blockIdx.x * blockDim.x + threadIdx.x;
    if (e >= N_EDGES) return;
    int dd = dst[e], ss = src[e], et = etype[e];
    float v = g_ssrc[ss] + g_sdst[dd] + g_srel[et];
    v = v > 0.0f ? v : SLOPE * v;
    float ex = __expf(-etime[e] * delta[0] * v);
    int pos = atomicAdd(&g_cur[dd], 1);
    g_pe[pos] = make_int2((ss << 8) | et, __float_as_int(ex));
}

// 6) aggregate + normalize + RMW into out. One warp per node; 8 lanes/edge,
//    4 edges in flight; float4 gathers; xor-shuffle reduction. Atomic-free.
__global__ void __launch_bounds__(256) k_agg(float* __restrict__ out) {
    int lane = threadIdx.x & 31;
    int grp = lane >> 3;       // edge slot 0..3
    int fl  = lane & 7;        // feature float4-pair index
    int totalWarps = gridDim.x * 8;
    const float4* hW4 = (const float4*)g_hW;
    const float4* rW4 = (const float4*)g_relW;
    float4* out4 = (float4*)out;

    for (int node = blockIdx.x * 8 + (threadIdx.x >> 5); node < N_NODES;
         node += totalWarps) {
        int beg = g_off[node], end = g_off[node + 1];
        if (beg == end) continue;               // fix-up kernel handles these
        float4 a0 = make_float4(0.f, 0.f, 0.f, 0.f);
        float4 a1 = make_float4(0.f, 0.f, 0.f, 0.f);
        float den = 0.0f;
        for (int i = beg + grp; i < end; i += 4) {
            int2 pe = __ldg(&g_pe[i]);          // broadcast within 8-lane group
            float x = __int_as_float(pe.y);
            int s = pe.x >> 8, et = pe.x & 255;
            float4 h0 = __ldg(&hW4[s * 16 + fl * 2]);
            float4 h1 = __ldg(&hW4[s * 16 + fl * 2 + 1]);
            float4 r0 = __ldg(&rW4[et * 16 + fl * 2]);
            float4 r1 = __ldg(&rW4[et * 16 + fl * 2 + 1]);
            den += x;
            a0.x = fmaf(x, h0.x + r0.x, a0.x);
            a0.y = fmaf(x, h0.y + r0.y, a0.y);
            a0.z = fmaf(x, h0.z + r0.z, a0.z);
            a0.w = fmaf(x, h0.w + r0.w, a0.w);
            a1.x = fmaf(x, h1.x + r1.x, a1.x);
            a1.y = fmaf(x, h1.y + r1.y, a1.y);
            a1.z = fmaf(x, h1.z + r1.z, a1.z);
            a1.w = fmaf(x, h1.w + r1.w, a1.w);
        }
        // sum across the 4 edge groups (lanes sharing fl)
        #pragma unroll
        for (int o = 8; o <= 16; o <<= 1) {
            a0.x += __shfl_xor_sync(0xffffffffu, a0.x, o);
            a0.y += __shfl_xor_sync(0xffffffffu, a0.y, o);
            a0.z += __shfl_xor_sync(0xffffffffu, a0.z, o);
            a0.w += __shfl_xor_sync(0xffffffffu, a0.w, o);
            a1.x += __shfl_xor_sync(0xffffffffu, a1.x, o);
            a1.y += __shfl_xor_sync(0xffffffffu, a1.y, o);
            a1.z += __shfl_xor_sync(0xffffffffu, a1.z, o);
            a1.w += __shfl_xor_sync(0xffffffffu, a1.w, o);
            den  += __shfl_xor_sync(0xffffffffu, den,  o);
        }
        if (lane < 16) {                        // grp 0 -> a0 half, grp 1 -> a1 half
            float inv = __fdividef(1.0f, den);
            float4 a = grp ? a1 : a0;
            int idx = node * 16 + fl * 2 + grp;
            float4 o = out4[idx];               // preloaded loop term h@Wl
            o.x = fmaf(a.x, inv, o.x);
            o.y = fmaf(a.y, inv, o.y);
            o.z = fmaf(a.z, inv, o.z);
            o.w = fmaf(a.w, inv, o.w);
            out4[idx] = o;
        }
    }
}

// 7) fix-up: zero-degree nodes get out = h + h@We (overwrites the h@Wl seed).
//    One warp per node; early-exit for deg>0 (expected: ~all of them).
__global__ void k_fix(const float* __restrict__ h, const float* __restrict__ We,
                      float* __restrict__ out) {
    int node = blockIdx.x * 8 + (threadIdx.x >> 5);
    if (node >= N_NODES) return;
    if (g_off[node + 1] != g_off[node]) return;
    int lane = threadIdx.x & 31;
    const float2* h2 = (const float2*)h;
    float2 hr = h2[node * 32 + lane];
    float lx = hr.x, ly = hr.y;
    for (int k = 0; k < 32; k++) {
        float ha = __shfl_sync(0xffffffffu, hr.x, k);
        float hb = __shfl_sync(0xffffffffu, hr.y, k);
        float2 w0 = ((const float2*)We)[(2 * k) * 32 + lane];
        float2 w1 = ((const float2*)We)[(2 * k + 1) * 32 + lane];
        lx = fmaf(ha, w0.x, fmaf(hb, w1.x, lx));
        ly = fmaf(ha, w0.y, fmaf(hb, w1.y, ly));
    }
    ((float2*)out)[node * 32 + lane] = make_float2(lx, ly);
}

extern "C" void kernel_launch(void* const* d_in, const int* in_sizes, int n_in,
                              void* d_out, int out_size) {
    const float* h     = (const float*)d_in[0];
    const float* rel   = (const float*)d_in[1];
    const float* Wn    = (const float*)d_in[2];
    const float* attn  = (const float*)d_in[3];
    const float* delta = (const float*)d_in[4];
    const float* Wl    = (const float*)d_in[5];
    const float* We    = (const float*)d_in[6];
    const float* etime = (const float*)d_in[7];
    const int*   src   = (const int*)d_in[8];
    const int*   dst   = (const int*)d_in[9];
    const int*   etype = (const int*)d_in[10];
    float* out = (float*)d_out;

    k_zero   <<<391, 256>>>();
    k_hw_s   <<<25000, 256>>>(h, Wn, Wl, attn, out);
    k_rel    <<<N_RELS, 64>>>(rel, Wn, attn);
    k_hist   <<<6250, 256>>>(dst);
    k_scan1  <<<SCAN_NB, 512>>>();
    k_scan2  <<<1, 256>>>();
    k_scan3  <<<SCAN_NB, 512>>>();
    k_scatter<<<6250, 256>>>(etime, src, dst, etype, delta);
    k_agg    <<<1480, 256>>>(out);
    k_fix    <<<12500, 256>>>(h, We, out);
}

// round 11
// speedup vs baseline: 1.9122x; 1.9122x over previous
#include <cuda_runtime.h>

#define N_NODES 100000
#define N_EDGES 1600000
#define D 64
#define N_RELS 200
#define SLOPE 0.01f
#define SCAN_NB 196            // ceil(100000/512)

// Scratch (static device globals — no allocation anywhere)
__device__ float g_hW[N_NODES * D];      // h @ W[:D]
__device__ float g_relW[N_RELS * D];     // rel_emb @ W[D:]
__device__ float g_ssrc[N_NODES];
__device__ float g_sdst[N_NODES];
__device__ float g_srel[N_RELS];
__device__ int   g_cnt[N_NODES];         // dst histogram
__device__ int   g_off[N_NODES + 1];     // CSR offsets
__device__ int   g_cur[N_NODES];         // scatter cursors
__device__ int   g_bsum[SCAN_NB];        // scan block sums
__device__ int2  g_pe[N_EDGES];          // dst-sorted (src<<8|etype, bits(ex))

__device__ __forceinline__ int warp_incl_scan(int v) {
    #pragma unroll
    for (int o = 1; o < 32; o <<= 1) {
        int t = __shfl_up_sync(0xffffffffu, v, o);
        if ((threadIdx.x & 31) >= o) v += t;
    }
    return v;
}

// ---------------------------------------------------------------------------
// 0) zero histogram
__global__ void k_zero() {
    int i = blockIdx.x * blockDim.x + threadIdx.x;
    if (i < N_NODES) g_cnt[i] = 0;
}

// 1) register-tiled dual GEMM: g_hW = h@Wn[:D], out = h@Wl (loop seed);
//    plus s_src = h@a1, s_dst = h@a2.  64 nodes per 256-thread block,
//    each thread computes a 4-node x 4-col tile for BOTH matrices.
__global__ void __launch_bounds__(256) k_gemm(const float* __restrict__ h,
                                              const float* __restrict__ Wn,
                                              const float* __restrict__ Wl,
                                              const float* __restrict__ attn,
                                              float* __restrict__ out) {
    __shared__ float sh[64][68];          // [node][feat], padded
    __shared__ float sWn[D * D];
    __shared__ float sWl[D * D];
    int t = threadIdx.x;
    int nodeBase = blockIdx.x * 64;

    // stage weights (coalesced float4)
    const float4* Wn4 = (const float4*)Wn;
    const float4* Wl4 = (const float4*)Wl;
    #pragma unroll
    for (int i = 0; i < 4; i++) {
        ((float4*)sWn)[t + 256 * i] = Wn4[t + 256 * i];
        ((float4*)sWl)[t + 256 * i] = Wl4[t + 256 * i];
    }
    // stage h tile (1024 float4, coalesced; row-major, conflict-free writes)
    #pragma unroll
    for (int i = 0; i < 4; i++) {
        int f = t + 256 * i;
        int n = f >> 4, kc = f & 15;
        int node = nodeBase + n;
        float4 v = (node < N_NODES) ? ((const float4*)h)[node * 16 + kc]
                                    : make_float4(0.f, 0.f, 0.f, 0.f);
        *(float4*)&sh[n][kc * 4] = v;
    }
    __syncthreads();

    // attention dots for the tile's nodes (threads 0..63; attn via const cache)
    if (t < 64) {
        int node = nodeBase + t;
        if (node < N_NODES) {
            float s1 = 0.0f, s2 = 0.0f;
            #pragma unroll
            for (int k = 0; k < D; k++) {
                float hv = sh[t][k];
                s1 = fmaf(hv, __ldg(&attn[k]), s1);
                s2 = fmaf(hv, __ldg(&attn[D + k]), s2);
            }
            g_ssrc[node] = s1;
            g_sdst[node] = s2;
        }
    }

    // GEMM: thread (tx,ty) -> nodes n0..n0+3, cols j0..j0+3
    int tx = t & 15, ty = t >> 4;
    int n0 = ty * 4, j0 = tx * 4;
    float4 an[4], al[4];
    #pragma unroll
    for (int p = 0; p < 4; p++) {
        an[p] = make_float4(0.f, 0.f, 0.f, 0.f);
        al[p] = make_float4(0.f, 0.f, 0.f, 0.f);
    }
    #pragma unroll 4
    for (int k = 0; k < D; k++) {
        float4 wn = *(const float4*)&sWn[k * D + j0];
        float4 wl = *(const float4*)&sWl[k * D + j0];
        #pragma unroll
        for (int p = 0; p < 4; p++) {
            float hv = sh[n0 + p][k];
            an[p].x = fmaf(hv, wn.x, an[p].x);
            an[p].y = fmaf(hv, wn.y, an[p].y);
            an[p].z = fmaf(hv, wn.z, an[p].z);
            an[p].w = fmaf(hv, wn.w, an[p].w);
            al[p].x = fmaf(hv, wl.x, al[p].x);
            al[p].y = fmaf(hv, wl.y, al[p].y);
            al[p].z = fmaf(hv, wl.z, al[p].z);
            al[p].w = fmaf(hv, wl.w, al[p].w);
        }
    }
    #pragma unroll
    for (int p = 0; p < 4; p++) {
        int node = nodeBase + n0 + p;
        if (node < N_NODES) {
            ((float4*)g_hW)[node * 16 + tx] = an[p];
            ((float4*)out)[node * 16 + tx]  = al[p];
        }
    }
}

// 2) relW = rel_emb @ Wn[D:], s_rel = rel_emb @ a3
__global__ void k_rel(const float* __restrict__ rel, const float* __restrict__ Wn,
                      const float* __restrict__ attn) {
    __shared__ float sr[D];
    int r = blockIdx.x, j = threadIdx.x;
    sr[j] = rel[r * D + j];
    __syncthreads();
    float acc = 0.0f;
    #pragma unroll
    for (int k = 0; k < D; k++) acc = fmaf(sr[k], Wn[(D + k) * D + j], acc);
    g_relW[r * D + j] = acc;
    if (j == 0) {
        float s = 0.0f;
        #pragma unroll
        for (int k = 0; k < D; k++) s = fmaf(sr[k], attn[2 * D + k], s);
        g_srel[r] = s;
    }
}

// 3) histogram of dst
__global__ void k_hist(const int* __restrict__ dst) {
    int e = blockIdx.x * blockDim.x + threadIdx.x;
    if (e < N_EDGES) atomicAdd(&g_cnt[dst[e]], 1);
}

// 4a) per-block exclusive scan of g_cnt (512/block)
__global__ void k_scan1() {
    __shared__ int ws[16];
    int i = blockIdx.x * 512 + threadIdx.x;
    int lane = threadIdx.x & 31, wid = threadIdx.x >> 5;
    int v = (i < N_NODES) ? g_cnt[i] : 0;
    int s = warp_incl_scan(v);
    if (lane == 31) ws[wid] = s;
    __syncthreads();
    if (wid == 0) {
        int t = (lane < 16) ? ws[lane] : 0;
        int ts = warp_incl_scan(t);
        if (lane < 16) ws[lane] = ts;
    }
    __syncthreads();
    int excl = s - v + (wid > 0 ? ws[wid - 1] : 0);
    if (i < N_NODES) g_off[i] = excl;
    if (threadIdx.x == 0) g_bsum[blockIdx.x] = ws[15];
}

// 4b) scan of block sums
__global__ void k_scan2() {
    __shared__ int ws[8];
    int tid = threadIdx.x;
    int lane = tid & 31, wid = tid >> 5;
    int v = (tid < SCAN_NB) ? g_bsum[tid] : 0;
    int s = warp_incl_scan(v);
    if (lane == 31) ws[wid] = s;
    __syncthreads();
    if (wid == 0) {
        int t = (lane < 8) ? ws[lane] : 0;
        int ts = warp_incl_scan(t);
        if (lane < 8) ws[lane] = ts;
    }
    __syncthreads();
    int excl = s - v + (wid > 0 ? ws[wid - 1] : 0);
    if (tid < SCAN_NB) g_bsum[tid] = excl;
}

// 4c) add block offsets; init cursors; sentinel
__global__ void k_scan3() {
    int i = blockIdx.x * 512 + threadIdx.x;
    if (i < N_NODES) {
        int o = g_off[i] + g_bsum[blockIdx.x];
        g_off[i] = o;
        g_cur[i] = o;
    }
    if (i == 0) g_off[N_NODES] = N_EDGES;
}

// 5) scatter: ex = exp(score), write dst-sorted packed (pk, ex) as one STG.64
__global__ void k_scatter(const float* __restrict__ etime, const int* __restrict__ src,
                          const int* __restrict__ dst, const int* __restrict__ etype,
                          const float* __restrict__ delta) {
    int e = blockIdx.x * blockDim.x + threadIdx.x;
    if (e >= N_EDGES) return;
    int dd = dst[e], ss = src[e], et = etype[e];
    float v = g_ssrc[ss] + g_sdst[dd] + g_srel[et];
    v = v > 0.0f ? v : SLOPE * v;
    float ex = __expf(-etime[e] * delta[0] * v);
    int pos = atomicAdd(&g_cur[dd], 1);
    g_pe[pos] = make_int2((ss << 8) | et, __float_as_int(ex));
}

// 6) aggregate + normalize + RMW into out. One warp per node; 8 lanes/edge,
//    4 edges in flight; CONSECUTIVE float4 gathers (one 128B line per group
//    LDG); xor-shuffle reduction. Atomic-free.
__global__ void __launch_bounds__(256) k_agg(float* __restrict__ out) {
    int lane = threadIdx.x & 31;
    int grp = lane >> 3;       // edge slot 0..3
    int fl  = lane & 7;        // float4 index within half-row
    int totalWarps = gridDim.x * 8;
    const float4* hW4 = (const float4*)g_hW;
    const float4* rW4 = (const float4*)g_relW;
    float4* out4 = (float4*)out;

    for (int node = blockIdx.x * 8 + (threadIdx.x >> 5); node < N_NODES;
         node += totalWarps) {
        int beg = g_off[node], end = g_off[node + 1];
        if (beg == end) continue;               // fix-up kernel handles these
        float4 a0 = make_float4(0.f, 0.f, 0.f, 0.f);  // features [4fl, 4fl+4)
        float4 a1 = make_float4(0.f, 0.f, 0.f, 0.f);  // features [32+4fl, ...)
        float den = 0.0f;
        for (int i = beg + grp; i < end; i += 4) {
            int2 pe = __ldg(&g_pe[i]);          // broadcast within 8-lane group
            float x = __int_as_float(pe.y);
            int s = pe.x >> 8, et = pe.x & 255;
            float4 h0 = __ldg(&hW4[s * 16 + fl]);
            float4 h1 = __ldg(&hW4[s * 16 + 8 + fl]);
            float4 r0 = __ldg(&rW4[et * 16 + fl]);
            float4 r1 = __ldg(&rW4[et * 16 + 8 + fl]);
            den += x;
            a0.x = fmaf(x, h0.x + r0.x, a0.x);
            a0.y = fmaf(x, h0.y + r0.y, a0.y);
            a0.z = fmaf(x, h0.z + r0.z, a0.z);
            a0.w = fmaf(x, h0.w + r0.w, a0.w);
            a1.x = fmaf(x, h1.x + r1.x, a1.x);
            a1.y = fmaf(x, h1.y + r1.y, a1.y);
            a1.z = fmaf(x, h1.z + r1.z, a1.z);
            a1.w = fmaf(x, h1.w + r1.w, a1.w);
        }
        // sum across the 4 edge groups (lanes sharing fl)
        #pragma unroll
        for (int o = 8; o <= 16; o <<= 1) {
            a0.x += __shfl_xor_sync(0xffffffffu, a0.x, o);
            a0.y += __shfl_xor_sync(0xffffffffu, a0.y, o);
            a0.z += __shfl_xor_sync(0xffffffffu, a0.z, o);
            a0.w += __shfl_xor_sync(0xffffffffu, a0.w, o);
            a1.x += __shfl_xor_sync(0xffffffffu, a1.x, o);
            a1.y += __shfl_xor_sync(0xffffffffu, a1.y, o);
            a1.z += __shfl_xor_sync(0xffffffffu, a1.z, o);
            a1.w += __shfl_xor_sync(0xffffffffu, a1.w, o);
            den  += __shfl_xor_sync(0xffffffffu, den,  o);
        }
        if (lane < 16) {                        // grp0 -> float4 fl; grp1 -> 8+fl
            float inv = __fdividef(1.0f, den);
            float4 a = grp ? a1 : a0;
            int idx = node * 16 + grp * 8 + fl;
            float4 o = out4[idx];               // preloaded loop term h@Wl
            o.x = fmaf(a.x, inv, o.x);
            o.y = fmaf(a.y, inv, o.y);
            o.z = fmaf(a.z, inv, o.z);
            o.w = fmaf(a.w, inv, o.w);
            out4[idx] = o;
        }
    }
}

// 7) fix-up: zero-degree nodes get out = h + h@We (overwrites the h@Wl seed).
__global__ void k_fix(const float* __restrict__ h, const float* __restrict__ We,
                      float* __restrict__ out) {
    int node = blockIdx.x * 8 + (threadIdx.x >> 5);
    if (node >= N_NODES) return;
    if (g_off[node + 1] != g_off[node]) return;
    int lane = threadIdx.x & 31;
    const float2* h2 = (const float2*)h;
    float2 hr = h2[node * 32 + lane];
    float lx = hr.x, ly = hr.y;
    for (int k = 0; k < 32; k++) {
        float ha = __shfl_sync(0xffffffffu, hr.x, k);
        float hb = __shfl_sync(0xffffffffu, hr.y, k);
        float2 w0 = ((const float2*)We)[(2 * k) * 32 + lane];
        float2 w1 = ((const float2*)We)[(2 * k + 1) * 32 + lane];
        lx = fmaf(ha, w0.x, fmaf(hb, w1.x, lx));
        ly = fmaf(ha, w0.y, fmaf(hb, w1.y, ly));
    }
    ((float2*)out)[node * 32 + lane] = make_float2(lx, ly);
}

extern "C" void kernel_launch(void* const* d_in, const int* in_sizes, int n_in,
                              void* d_out, int out_size) {
    const float* h     = (const float*)d_in[0];
    const float* rel   = (const float*)d_in[1];
    const float* Wn    = (const float*)d_in[2];
    const float* attn  = (const float*)d_in[3];
    const float* delta = (const float*)d_in[4];
    const float* Wl    = (const float*)d_in[5];
    const float* We    = (const float*)d_in[6];
    const float* etime = (const float*)d_in[7];
    const int*   src   = (const int*)d_in[8];
    const int*   dst   = (const int*)d_in[9];
    const int*   etype = (const int*)d_in[10];
    float* out = (float*)d_out;

    k_zero   <<<391, 256>>>();
    k_gemm   <<<1563, 256>>>(h, Wn, Wl, attn, out);
    k_rel    <<<N_RELS, 64>>>(rel, Wn, attn);
    k_hist   <<<6250, 256>>>(dst);
    k_scan1  <<<SCAN_NB, 512>>>();
    k_scan2  <<<1, 256>>>();
    k_scan3  <<<SCAN_NB, 512>>>();
    k_scatter<<<6250, 256>>>(etime, src, dst, etype, delta);
    k_agg    <<<1480, 256>>>(out);
    k_fix    <<<12500, 256>>>(h, We, out);
}

// round 13
// speedup vs baseline: 1.9392x; 1.0141x over previous
#include <cuda_runtime.h>

#define N_NODES 100000
#define N_EDGES 1600000
#define D 64
#define N_RELS 200
#define SLOPE 0.01f
#define SCAN_NB 196            // ceil(100000/512)
#define GEMM_NB 1563           // ceil(100000/64)
#define REL_NB 50              // 200 rels / 4 per block

typedef unsigned long long u64;

// Scratch (static device globals — no allocation anywhere)
__device__ float g_hW[N_NODES * D];      // h @ W[:D]
__device__ float g_relW[N_RELS * D];     // rel_emb @ W[D:]
__device__ float g_ssrc[N_NODES];
__device__ float g_sdst[N_NODES];
__device__ float g_srel[N_RELS];
__device__ int   g_cnt[N_NODES];         // dst histogram
__device__ int   g_off[N_NODES + 1];     // CSR offsets
__device__ int   g_cur[N_NODES];         // scatter cursors
__device__ int   g_bsum[SCAN_NB];        // scan block sums
__device__ int2  g_pe[N_EDGES];          // dst-sorted (src<<8|etype, bits(ex))

__device__ __forceinline__ u64 pack2(float lo, float hi) {
    u64 r;
    asm("mov.b64 %0, {%1, %2};" : "=l"(r) : "f"(lo), "f"(hi));
    return r;
}
__device__ __forceinline__ void fma2(u64& d, u64 a, u64 b) {
    asm("fma.rn.f32x2 %0, %1, %2, %0;" : "+l"(d) : "l"(a), "l"(b));
}

__device__ __forceinline__ int warp_incl_scan(int v) {
    #pragma unroll
    for (int o = 1; o < 32; o <<= 1) {
        int t = __shfl_up_sync(0xffffffffu, v, o);
        if ((threadIdx.x & 31) >= o) v += t;
    }
    return v;
}

// ---------------------------------------------------------------------------
// 1) fused front kernel:
//    blocks [0, GEMM_NB): register-tiled dual GEMM with packed f32x2 FMA:
//       g_hW = h@Wn[:D], out = h@Wl (loop seed), s_src/s_dst dots.
//    blocks [GEMM_NB, GEMM_NB+REL_NB): relW = rel@Wn[D:], s_rel = rel@a3.
//    all blocks: zero a slice of g_cnt.
__global__ void __launch_bounds__(256) k_gemm(const float* __restrict__ h,
                                              const float* __restrict__ rel,
                                              const float* __restrict__ Wn,
                                              const float* __restrict__ Wl,
                                              const float* __restrict__ attn,
                                              float* __restrict__ out) {
    int t = threadIdx.x;
    // zero histogram slice (all blocks; 1613*256 = 412928 >= N_NODES)
    int zi = blockIdx.x * 256 + t;
    if (zi < N_NODES) g_cnt[zi] = 0;

    if (blockIdx.x >= GEMM_NB) {
        // ---- relation blocks: 4 relations x 64 threads ----
        __shared__ float sr[4][D];
        int rl = t >> 6, j = t & 63;
        int r = (blockIdx.x - GEMM_NB) * 4 + rl;
        sr[rl][j] = rel[r * D + j];
        __syncthreads();
        float acc = 0.0f;
        #pragma unroll
        for (int k = 0; k < D; k++)
            acc = fmaf(sr[rl][k], __ldg(&Wn[(D + k) * D + j]), acc);
        g_relW[r * D + j] = acc;
        if (j == 0) {
            float s = 0.0f;
            #pragma unroll
            for (int k = 0; k < D; k++)
                s = fmaf(sr[rl][k], __ldg(&attn[2 * D + k]), s);
            g_srel[r] = s;
        }
        return;
    }

    // ---- GEMM blocks ----
    __shared__ float sh[64][68];          // [node][feat], padded
    __shared__ float sWn[D * D];
    __shared__ float sWl[D * D];
    int nodeBase = blockIdx.x * 64;

    const float4* Wn4 = (const float4*)Wn;
    const float4* Wl4 = (const float4*)Wl;
    #pragma unroll
    for (int i = 0; i < 4; i++) {
        ((float4*)sWn)[t + 256 * i] = Wn4[t + 256 * i];
        ((float4*)sWl)[t + 256 * i] = Wl4[t + 256 * i];
    }
    #pragma unroll
    for (int i = 0; i < 4; i++) {
        int f = t + 256 * i;
        int n = f >> 4, kc = f & 15;
        int node = nodeBase + n;
        float4 v = (node < N_NODES) ? ((const float4*)h)[node * 16 + kc]
                                    : make_float4(0.f, 0.f, 0.f, 0.f);
        *(float4*)&sh[n][kc * 4] = v;
    }
    __syncthreads();

    // attention dots for the tile's nodes
    if (t < 64) {
        int node = nodeBase + t;
        if (node < N_NODES) {
            float s1 = 0.0f, s2 = 0.0f;
            #pragma unroll
            for (int k = 0; k < D; k++) {
                float hv = sh[t][k];
                s1 = fmaf(hv, __ldg(&attn[k]), s1);
                s2 = fmaf(hv, __ldg(&attn[D + k]), s2);
            }
            g_ssrc[node] = s1;
            g_sdst[node] = s2;
        }
    }

    // GEMM: thread (tx,ty) -> nodes n0..n0+3, cols j0..j0+3, packed f32x2
    int tx = t & 15, ty = t >> 4;
    int n0 = ty * 4, j0 = tx * 4;
    u64 an2[4][2], al2[4][2];
    #pragma unroll
    for (int p = 0; p < 4; p++) {
        an2[p][0] = an2[p][1] = 0ull;   // bits of (0.f, 0.f)
        al2[p][0] = al2[p][1] = 0ull;
    }
    #pragma unroll 4
    for (int k = 0; k < D; k++) {
        ulonglong2 wn2 = *(const ulonglong2*)&sWn[k * D + j0];  // (w0,w1),(w2,w3)
        ulonglong2 wl2 = *(const ulonglong2*)&sWl[k * D + j0];
        #pragma unroll
        for (int p = 0; p < 4; p++) {
            u64 h2 = pack2(sh[n0 + p][k], sh[n0 + p][k]);
            fma2(an2[p][0], h2, wn2.x);
            fma2(an2[p][1], h2, wn2.y);
            fma2(al2[p][0], h2, wl2.x);
            fma2(al2[p][1], h2, wl2.y);
        }
    }
    #pragma unroll
    for (int p = 0; p < 4; p++) {
        int node = nodeBase + n0 + p;
        if (node < N_NODES) {
            ((ulonglong2*)g_hW)[node * 16 + tx] = make_ulonglong2(an2[p][0], an2[p][1]);
            ((ulonglong2*)out)[node * 16 + tx]  = make_ulonglong2(al2[p][0], al2[p][1]);
        }
    }
}

// 3) histogram of dst
__global__ void k_hist(const int* __restrict__ dst) {
    int e = blockIdx.x * blockDim.x + threadIdx.x;
    if (e < N_EDGES) atomicAdd(&g_cnt[dst[e]], 1);
}

// 4a) per-block exclusive scan of g_cnt (512/block)
__global__ void k_scan1() {
    __shared__ int ws[16];
    int i = blockIdx.x * 512 + threadIdx.x;
    int lane = threadIdx.x & 31, wid = threadIdx.x >> 5;
    int v = (i < N_NODES) ? g_cnt[i] : 0;
    int s = warp_incl_scan(v);
    if (lane == 31) ws[wid] = s;
    __syncthreads();
    if (wid == 0) {
        int t = (lane < 16) ? ws[lane] : 0;
        int ts = warp_incl_scan(t);
        if (lane < 16) ws[lane] = ts;
    }
    __syncthreads();
    int excl = s - v + (wid > 0 ? ws[wid - 1] : 0);
    if (i < N_NODES) g_off[i] = excl;
    if (threadIdx.x == 0) g_bsum[blockIdx.x] = ws[15];
}

// 4b) scan of block sums
__global__ void k_scan2() {
    __shared__ int ws[8];
    int tid = threadIdx.x;
    int lane = tid & 31, wid = tid >> 5;
    int v = (tid < SCAN_NB) ? g_bsum[tid] : 0;
    int s = warp_incl_scan(v);
    if (lane == 31) ws[wid] = s;
    __syncthreads();
    if (wid == 0) {
        int t = (lane < 8) ? ws[lane] : 0;
        int ts = warp_incl_scan(t);
        if (lane < 8) ws[lane] = ts;
    }
    __syncthreads();
    int excl = s - v + (wid > 0 ? ws[wid - 1] : 0);
    if (tid < SCAN_NB) g_bsum[tid] = excl;
}

// 4c) add block offsets; init cursors; sentinel
__global__ void k_scan3() {
    int i = blockIdx.x * 512 + threadIdx.x;
    if (i < N_NODES) {
        int o = g_off[i] + g_bsum[blockIdx.x];
        g_off[i] = o;
        g_cur[i] = o;
    }
    if (i == 0) g_off[N_NODES] = N_EDGES;
}

// 5) scatter: ex = exp(score), write dst-sorted packed (pk, ex) as one STG.64
__global__ void k_scatter(const float* __restrict__ etime, const int* __restrict__ src,
                          const int* __restrict__ dst, const int* __restrict__ etype,
                          const float* __restrict__ delta) {
    int e = blockIdx.x * blockDim.x + threadIdx.x;
    if (e >= N_EDGES) return;
    int dd = dst[e], ss = src[e], et = etype[e];
    float v = g_ssrc[ss] + g_sdst[dd] + g_srel[et];
    v = v > 0.0f ? v : SLOPE * v;
    float ex = __expf(-etime[e] * delta[0] * v);
    int pos = atomicAdd(&g_cur[dd], 1);
    g_pe[pos] = make_int2((ss << 8) | et, __float_as_int(ex));
}

// 6) aggregate + normalize + RMW into out. One warp per node; 8 lanes/edge,
//    4 edges in flight; consecutive float4 gathers; xor-shuffle reduction.
__global__ void __launch_bounds__(256) k_agg(float* __restrict__ out) {
    int lane = threadIdx.x & 31;
    int grp = lane >> 3;       // edge slot 0..3
    int fl  = lane & 7;        // float4 index within half-row
    int totalWarps = gridDim.x * 8;
    const float4* hW4 = (const float4*)g_hW;
    const float4* rW4 = (const float4*)g_relW;
    float4* out4 = (float4*)out;

    for (int node = blockIdx.x * 8 + (threadIdx.x >> 5); node < N_NODES;
         node += totalWarps) {
        int beg = g_off[node], end = g_off[node + 1];
        if (beg == end) continue;               // fix-up kernel handles these
        float4 a0 = make_float4(0.f, 0.f, 0.f, 0.f);  // features [4fl, 4fl+4)
        float4 a1 = make_float4(0.f, 0.f, 0.f, 0.f);  // features [32+4fl, ...)
        float den = 0.0f;
        for (int i = beg + grp; i < end; i += 4) {
            int2 pe = __ldg(&g_pe[i]);          // broadcast within 8-lane group
            float x = __int_as_float(pe.y);
            int s = pe.x >> 8, et = pe.x & 255;
            float4 h0 = __ldg(&hW4[s * 16 + fl]);
            float4 h1 = __ldg(&hW4[s * 16 + 8 + fl]);
            float4 r0 = __ldg(&rW4[et * 16 + fl]);
            float4 r1 = __ldg(&rW4[et * 16 + 8 + fl]);
            den += x;
            a0.x = fmaf(x, h0.x + r0.x, a0.x);
            a0.y = fmaf(x, h0.y + r0.y, a0.y);
            a0.z = fmaf(x, h0.z + r0.z, a0.z);
            a0.w = fmaf(x, h0.w + r0.w, a0.w);
            a1.x = fmaf(x, h1.x + r1.x, a1.x);
            a1.y = fmaf(x, h1.y + r1.y, a1.y);
            a1.z = fmaf(x, h1.z + r1.z, a1.z);
            a1.w = fmaf(x, h1.w + r1.w, a1.w);
        }
        #pragma unroll
        for (int o = 8; o <= 16; o <<= 1) {
            a0.x += __shfl_xor_sync(0xffffffffu, a0.x, o);
            a0.y += __shfl_xor_sync(0xffffffffu, a0.y, o);
            a0.z += __shfl_xor_sync(0xffffffffu, a0.z, o);
            a0.w += __shfl_xor_sync(0xffffffffu, a0.w, o);
            a1.x += __shfl_xor_sync(0xffffffffu, a1.x, o);
            a1.y += __shfl_xor_sync(0xffffffffu, a1.y, o);
            a1.z += __shfl_xor_sync(0xffffffffu, a1.z, o);
            a1.w += __shfl_xor_sync(0xffffffffu, a1.w, o);
            den  += __shfl_xor_sync(0xffffffffu, den,  o);
        }
        if (lane < 16) {                        // grp0 -> float4 fl; grp1 -> 8+fl
            float inv = __fdividef(1.0f, den);
            float4 a = grp ? a1 : a0;
            int idx = node * 16 + grp * 8 + fl;
            float4 o = out4[idx];               // preloaded loop term h@Wl
            o.x = fmaf(a.x, inv, o.x);
            o.y = fmaf(a.y, inv, o.y);
            o.z = fmaf(a.z, inv, o.z);
            o.w = fmaf(a.w, inv, o.w);
            out4[idx] = o;
        }
    }
}

// 7) fix-up: zero-degree nodes get out = h + h@We (overwrites the h@Wl seed).
__global__ void k_fix(const float* __restrict__ h, const float* __restrict__ We,
                      float* __restrict__ out) {
    int node = blockIdx.x * 8 + (threadIdx.x >> 5);
    if (node >= N_NODES) return;
    if (g_off[node + 1] != g_off[node]) return;
    int lane = threadIdx.x & 31;
    const float2* h2 = (const float2*)h;
    float2 hr = h2[node * 32 + lane];
    float lx = hr.x, ly = hr.y;
    for (int k = 0; k < 32; k++) {
        float ha = __shfl_sync(0xffffffffu, hr.x, k);
        float hb = __shfl_sync(0xffffffffu, hr.y, k);
        float2 w0 = ((const float2*)We)[(2 * k) * 32 + lane];
        float2 w1 = ((const float2*)We)[(2 * k + 1) * 32 + lane];
        lx = fmaf(ha, w0.x, fmaf(hb, w1.x, lx));
        ly = fmaf(ha, w0.y, fmaf(hb, w1.y, ly));
    }
    ((float2*)out)[node * 32 + lane] = make_float2(lx, ly);
}

extern "C" void kernel_launch(void* const* d_in, const int* in_sizes, int n_in,
                              void* d_out, int out_size) {
    const float* h     = (const float*)d_in[0];
    const float* rel   = (const float*)d_in[1];
    const float* Wn    = (const float*)d_in[2];
    const float* attn  = (const float*)d_in[3];
    const float* delta = (const float*)d_in[4];
    const float* Wl    = (const float*)d_in[5];
    const float* We    = (const float*)d_in[6];
    const float* etime = (const float*)d_in[7];
    const int*   src   = (const int*)d_in[8];
    const int*   dst   = (const int*)d_in[9];
    const int*   etype = (const int*)d_in[10];
    float* out = (float*)d_out;

    k_gemm   <<<GEMM_NB + REL_NB, 256>>>(h, rel, Wn, Wl, attn, out);
    k_hist   <<<6250, 256>>>(dst);
    k_scan1  <<<SCAN_NB, 512>>>();
    k_scan2  <<<1, 256>>>();
    k_scan3  <<<SCAN_NB, 512>>>();
    k_scatter<<<6250, 256>>>(etime, src, dst, etype, delta);
    k_agg    <<<1480, 256>>>(out);
    k_fix    <<<12500, 256>>>(h, We, out);
}

// round 14
// speedup vs baseline: 2.1365x; 1.1017x over previous
#include <cuda_runtime.h>

#define N_NODES 100000
#define N_EDGES 1600000
#define D 64
#define N_RELS 200
#define SLOPE 0.01f
#define SCAN_NB 196            // ceil(100000/512)
#define GEMM_NB 1563           // ceil(100000/64)
#define REL_NB 50              // 200 rels / 4 per block
#define TOTAL_NB (GEMM_NB + REL_NB)
#define EPB 992                // ceil(N_EDGES / TOTAL_NB)

typedef unsigned long long u64;

// Scratch (static device globals — zero-initialized at load; every run leaves
// the mutable control state back at zero, so graph replays are deterministic)
__device__ float g_hW[N_NODES * D];      // h @ W[:D]
__device__ float g_relW[N_RELS * D];     // rel_emb @ W[D:]
__device__ float g_ssrc[N_NODES];
__device__ float g_sdst[N_NODES];
__device__ float g_srel[N_RELS];
__device__ int   g_cnt[N_NODES];         // dst histogram (self-cleaned in k_scan)
__device__ int   g_off[N_NODES + 1];     // CSR offsets
__device__ int   g_cur[N_NODES];         // scatter cursors
__device__ int   g_aggr[SCAN_NB];        // per-block sums
__device__ int   g_bpref[SCAN_NB];       // per-block exclusive prefixes
__device__ int   g_done_cnt;             // arrival counter (reset in k_scatter)
__device__ int   g_pref_ready;           // release flag   (reset in k_scatter)
__device__ int2  g_pe[N_EDGES];          // dst-sorted (src<<8|etype, bits(ex))

__device__ __forceinline__ u64 pack2(float lo, float hi) {
    u64 r;
    asm("mov.b64 %0, {%1, %2};" : "=l"(r) : "f"(lo), "f"(hi));
    return r;
}
__device__ __forceinline__ void fma2(u64& d, u64 a, u64 b) {
    asm("fma.rn.f32x2 %0, %1, %2, %0;" : "+l"(d) : "l"(a), "l"(b));
}

__device__ __forceinline__ int warp_incl_scan(int v) {
    #pragma unroll
    for (int o = 1; o < 32; o <<= 1) {
        int t = __shfl_up_sync(0xffffffffu, v, o);
        if ((threadIdx.x & 31) >= o) v += t;
    }
    return v;
}

// ---------------------------------------------------------------------------
// 1) fused front kernel:
//    ALL blocks: histogram a 992-edge slice of dst (overlaps with compute).
//    blocks [0, GEMM_NB): register-tiled dual GEMM (f32x2 packed FMA):
//       g_hW = h@Wn[:D], out = h@Wl (loop seed), s_src/s_dst dots.
//    blocks [GEMM_NB, TOTAL_NB): relW = rel@Wn[D:], s_rel = rel@a3.
__global__ void __launch_bounds__(256) k_gemm(const float* __restrict__ h,
                                              const float* __restrict__ rel,
                                              const float* __restrict__ Wn,
                                              const float* __restrict__ Wl,
                                              const float* __restrict__ attn,
                                              const int* __restrict__ dst,
                                              float* __restrict__ out) {
    int t = threadIdx.x;

    // edge-histogram slice (g_cnt is zero on entry: zero-init / self-cleaned)
    int ebase = blockIdx.x * EPB;
    #pragma unroll
    for (int i = 0; i < EPB / 256 + 1; i++) {
        int e = ebase + t + i * 256;
        if (e < ebase + EPB && e < N_EDGES) atomicAdd(&g_cnt[dst[e]], 1);
    }

    if (blockIdx.x >= GEMM_NB) {
        // ---- relation blocks: 4 relations x 64 threads ----
        __shared__ float sr[4][D];
        int rl = t >> 6, j = t & 63;
        int r = (blockIdx.x - GEMM_NB) * 4 + rl;
        sr[rl][j] = rel[r * D + j];
        __syncthreads();
        float acc = 0.0f;
        #pragma unroll
        for (int k = 0; k < D; k++)
            acc = fmaf(sr[rl][k], __ldg(&Wn[(D + k) * D + j]), acc);
        g_relW[r * D + j] = acc;
        if (j == 0) {
            float s = 0.0f;
            #pragma unroll
            for (int k = 0; k < D; k++)
                s = fmaf(sr[rl][k], __ldg(&attn[2 * D + k]), s);
            g_srel[r] = s;
        }
        return;
    }

    // ---- GEMM blocks ----
    __shared__ float sh[64][68];          // [node][feat], padded
    __shared__ float sWn[D * D];
    __shared__ float sWl[D * D];
    int nodeBase = blockIdx.x * 64;

    const float4* Wn4 = (const float4*)Wn;
    const float4* Wl4 = (const float4*)Wl;
    #pragma unroll
    for (int i = 0; i < 4; i++) {
        ((float4*)sWn)[t + 256 * i] = Wn4[t + 256 * i];
        ((float4*)sWl)[t + 256 * i] = Wl4[t + 256 * i];
    }
    #pragma unroll
    for (int i = 0; i < 4; i++) {
        int f = t + 256 * i;
        int n = f >> 4, kc = f & 15;
        int node = nodeBase + n;
        float4 v = (node < N_NODES) ? ((const float4*)h)[node * 16 + kc]
                                    : make_float4(0.f, 0.f, 0.f, 0.f);
        *(float4*)&sh[n][kc * 4] = v;
    }
    __syncthreads();

    // attention dots for the tile's nodes
    if (t < 64) {
        int node = nodeBase + t;
        if (node < N_NODES) {
            float s1 = 0.0f, s2 = 0.0f;
            #pragma unroll
            for (int k = 0; k < D; k++) {
                float hv = sh[t][k];
                s1 = fmaf(hv, __ldg(&attn[k]), s1);
                s2 = fmaf(hv, __ldg(&attn[D + k]), s2);
            }
            g_ssrc[node] = s1;
            g_sdst[node] = s2;
        }
    }

    // GEMM: thread (tx,ty) -> nodes n0..n0+3, cols j0..j0+3, packed f32x2
    int tx = t & 15, ty = t >> 4;
    int n0 = ty * 4, j0 = tx * 4;
    u64 an2[4][2], al2[4][2];
    #pragma unroll
    for (int p = 0; p < 4; p++) {
        an2[p][0] = an2[p][1] = 0ull;
        al2[p][0] = al2[p][1] = 0ull;
    }
    #pragma unroll 4
    for (int k = 0; k < D; k++) {
        ulonglong2 wn2 = *(const ulonglong2*)&sWn[k * D + j0];
        ulonglong2 wl2 = *(const ulonglong2*)&sWl[k * D + j0];
        #pragma unroll
        for (int p = 0; p < 4; p++) {
            u64 h2 = pack2(sh[n0 + p][k], sh[n0 + p][k]);
            fma2(an2[p][0], h2, wn2.x);
            fma2(an2[p][1], h2, wn2.y);
            fma2(al2[p][0], h2, wl2.x);
            fma2(al2[p][1], h2, wl2.y);
        }
    }
    #pragma unroll
    for (int p = 0; p < 4; p++) {
        int node = nodeBase + n0 + p;
        if (node < N_NODES) {
            ((ulonglong2*)g_hW)[node * 16 + tx] = make_ulonglong2(an2[p][0], an2[p][1]);
            ((ulonglong2*)out)[node * 16 + tx]  = make_ulonglong2(al2[p][0], al2[p][1]);
        }
    }
}

// 2) single-kernel exclusive scan of g_cnt -> g_off/g_cur (+ self-clean g_cnt).
//    196 fully-resident blocks; last-arriving block scans the block sums and
//    releases everyone via g_pref_ready.
__global__ void __launch_bounds__(512) k_scan() {
    __shared__ int ws[16];
    __shared__ int sLast;
    int t = threadIdx.x, lane = t & 31, wid = t >> 5;
    int i = blockIdx.x * 512 + t;

    int v = (i < N_NODES) ? g_cnt[i] : 0;
    if (i < N_NODES) g_cnt[i] = 0;          // self-clean for next run
    int s = warp_incl_scan(v);
    if (lane == 31) ws[wid] = s;
    __syncthreads();
    if (wid == 0) {
        int x = (lane < 16) ? ws[lane] : 0;
        int xs = warp_incl_scan(x);
        if (lane < 16) ws[lane] = xs;
    }
    __syncthreads();
    int excl = s - v + (wid ? ws[wid - 1] : 0);
    int total = ws[15];

    if (t == 0) {
        g_aggr[blockIdx.x] = total;
        __threadfence();
        int old = atomicAdd(&g_done_cnt, 1);
        sLast = (old == SCAN_NB - 1);
    }
    __syncthreads();

    if (sLast && wid == 0) {                // last block: level-2 scan (1 warp)
        int carry = 0;
        for (int base = 0; base < SCAN_NB; base += 32) {
            int idx = base + lane;
            int a = (idx < SCAN_NB) ? *(volatile int*)&g_aggr[idx] : 0;
            int as = warp_incl_scan(a);
            if (idx < SCAN_NB) g_bpref[idx] = carry + as - a;
            carry += __shfl_sync(0xffffffffu, as, 31);
        }
        __threadfence();
        if (lane == 0) *(volatile int*)&g_pref_ready = 1;
    }

    if (t == 0) {
        while (*(volatile int*)&g_pref_ready == 0) __nanosleep(64);
    }
    __syncthreads();
    __threadfence();
    int boff = *(volatile int*)&g_bpref[blockIdx.x];
    int off = boff + excl;
    if (i < N_NODES) { g_off[i] = off; g_cur[i] = off; }
    if (i == 0) g_off[N_NODES] = N_EDGES;
}

// 3) scatter: ex = exp(score), write dst-sorted packed (pk, ex) as one STG.64.
//    Also resets the scan control words for the next graph replay.
__global__ void k_scatter(const float* __restrict__ etime, const int* __restrict__ src,
                          const int* __restrict__ dst, const int* __restrict__ etype,
                          const float* __restrict__ delta) {
    if (blockIdx.x == 0 && threadIdx.x == 0) { g_done_cnt = 0; g_pref_ready = 0; }
    int e = blockIdx.x * blockDim.x + threadIdx.x;
    if (e >= N_EDGES) return;
    int dd = dst[e], ss = src[e], et = etype[e];
    float v = g_ssrc[ss] + g_sdst[dd] + g_srel[et];
    v = v > 0.0f ? v : SLOPE * v;
    float ex = __expf(-etime[e] * delta[0] * v);
    int pos = atomicAdd(&g_cur[dd], 1);
    g_pe[pos] = make_int2((ss << 8) | et, __float_as_int(ex));
}

// 4) aggregate + normalize + RMW into out. One warp per node; 8 lanes/edge,
//    4 edges in flight; consecutive float4 gathers; xor-shuffle reduction.
//    Zero-degree nodes handled inline (out = h + h@We).
__global__ void __launch_bounds__(256) k_agg(const float* __restrict__ h,
                                             const float* __restrict__ We,
                                             float* __restrict__ out) {
    int lane = threadIdx.x & 31;
    int grp = lane >> 3;       // edge slot 0..3
    int fl  = lane & 7;        // float4 index within half-row
    int totalWarps = gridDim.x * 8;
    const float4* hW4 = (const float4*)g_hW;
    const float4* rW4 = (const float4*)g_relW;
    float4* out4 = (float4*)out;

    for (int node = blockIdx.x * 8 + (threadIdx.x >> 5); node < N_NODES;
         node += totalWarps) {
        int beg = g_off[node], end = g_off[node + 1];
        if (beg == end) {                    // rare: out = h + h@We
            float2 hr = ((const float2*)h)[node * 32 + lane];
            float lx = hr.x, ly = hr.y;
            for (int k = 0; k < 32; k++) {
                float ha = __shfl_sync(0xffffffffu, hr.x, k);
                float hb = __shfl_sync(0xffffffffu, hr.y, k);
                float2 w0 = __ldg(&((const float2*)We)[(2 * k) * 32 + lane]);
                float2 w1 = __ldg(&((const float2*)We)[(2 * k + 1) * 32 + lane]);
                lx = fmaf(ha, w0.x, fmaf(hb, w1.x, lx));
                ly = fmaf(ha, w0.y, fmaf(hb, w1.y, ly));
            }
            ((float2*)out)[node * 32 + lane] = make_float2(lx, ly);
            continue;
        }
        float4 a0 = make_float4(0.f, 0.f, 0.f, 0.f);  // features [4fl, 4fl+4)
        float4 a1 = make_float4(0.f, 0.f, 0.f, 0.f);  // features [32+4fl, ...)
        float den = 0.0f;
        for (int i = beg + grp; i < end; i += 4) {
            int2 pe = __ldg(&g_pe[i]);          // broadcast within 8-lane group
            float x = __int_as_float(pe.y);
            int s = pe.x >> 8, et = pe.x & 255;
            float4 h0 = __ldg(&hW4[s * 16 + fl]);
            float4 h1 = __ldg(&hW4[s * 16 + 8 + fl]);
            float4 r0 = __ldg(&rW4[et * 16 + fl]);
            float4 r1 = __ldg(&rW4[et * 16 + 8 + fl]);
            den += x;
            a0.x = fmaf(x, h0.x + r0.x, a0.x);
            a0.y = fmaf(x, h0.y + r0.y, a0.y);
            a0.z = fmaf(x, h0.z + r0.z, a0.z);
            a0.w = fmaf(x, h0.w + r0.w, a0.w);
            a1.x = fmaf(x, h1.x + r1.x, a1.x);
            a1.y = fmaf(x, h1.y + r1.y, a1.y);
            a1.z = fmaf(x, h1.z + r1.z, a1.z);
            a1.w = fmaf(x, h1.w + r1.w, a1.w);
        }
        #pragma unroll
        for (int o = 8; o <= 16; o <<= 1) {
            a0.x += __shfl_xor_sync(0xffffffffu, a0.x, o);
            a0.y += __shfl_xor_sync(0xffffffffu, a0.y, o);
            a0.z += __shfl_xor_sync(0xffffffffu, a0.z, o);
            a0.w += __shfl_xor_sync(0xffffffffu, a0.w, o);
            a1.x += __shfl_xor_sync(0xffffffffu, a1.x, o);
            a1.y += __shfl_xor_sync(0xffffffffu, a1.y, o);
            a1.z += __shfl_xor_sync(0xffffffffu, a1.z, o);
            a1.w += __shfl_xor_sync(0xffffffffu, a1.w, o);
            den  += __shfl_xor_sync(0xffffffffu, den,  o);
        }
        if (lane < 16) {                        // grp0 -> float4 fl; grp1 -> 8+fl
            float inv = __fdividef(1.0f, den);
            float4 a = grp ? a1 : a0;
            int idx = node * 16 + grp * 8 + fl;
            float4 o = out4[idx];               // preloaded loop term h@Wl
            o.x = fmaf(a.x, inv, o.x);
            o.y = fmaf(a.y, inv, o.y);
            o.z = fmaf(a.z, inv, o.z);
            o.w = fmaf(a.w, inv, o.w);
            out4[idx] = o;
        }
    }
}

extern "C" void kernel_launch(void* const* d_in, const int* in_sizes, int n_in,
                              void* d_out, int out_size) {
    const float* h     = (const float*)d_in[0];
    const float* rel   = (const float*)d_in[1];
    const float* Wn    = (const float*)d_in[2];
    const float* attn  = (const float*)d_in[3];
    const float* delta = (const float*)d_in[4];
    const float* Wl    = (const float*)d_in[5];
    const float* We    = (const float*)d_in[6];
    const float* etime = (const float*)d_in[7];
    const int*   src   = (const int*)d_in[8];
    const int*   dst   = (const int*)d_in[9];
    const int*   etype = (const int*)d_in[10];
    float* out = (float*)d_out;

    k_gemm   <<<TOTAL_NB, 256>>>(h, rel, Wn, Wl, attn, dst, out);
    k_scan   <<<SCAN_NB, 512>>>();
    k_scatter<<<6250, 256>>>(etime, src, dst, etype, delta);
    k_agg    <<<1480, 256>>>(h, We, out);
}